// round 11
// baseline (speedup 1.0000x reference)
#include <cuda_runtime.h>
#include <cuda_bf16.h>
#include <cstdint>

// Problem constants
#define VCODES 8192
#define DDIM   256
#define MROWS  32768      // 8 * 16*16*16
#define SPAT   4096       // 16*16*16

// Output layout (concatenated f32)
#define O_QUANT 0ul
#define O_IDX   8388608ul
#define O_QD    8421376ul
#define O_NEWN  8421377ul
#define O_ZAVG  8429569ul
#define O_NEWW  10526721ul

#define MARGIN 3.0f

// ---------------------------------------------------------------------------
// Scratch (device globals; no allocations allowed)
__device__ unsigned long long g_best[MROWS];
__device__ int   g_idx[MROWS];
__device__ float g_counts[VCODES];
__device__ float g_encsum[VCODES * DDIM];
__device__ float g_wsq[VCODES];
__device__ float g_sumN;
__device__ float g_qd;
__device__ __nv_bfloat16 g_abf[MROWS * DDIM];    // flat x, bf16
__device__ __nv_bfloat16 g_wbf[VCODES * DDIM];   // weight, bf16
__device__ __nv_bfloat16 g_scores[(size_t)MROWS * VCODES];  // coarse scores

// ---------------------------------------------------------------------------
__device__ __forceinline__ uint32_t smem_u32(const void* p) {
    uint32_t a;
    asm("{ .reg .u64 t; cvta.to.shared.u64 t, %1; cvt.u32.u64 %0, t; }" : "=r"(a) : "l"(p));
    return a;
}
__device__ __forceinline__ void cp16(uint32_t dst, const void* src) {
    asm volatile("cp.async.cg.shared.global [%0], [%1], 16;" :: "r"(dst), "l"(src) : "memory");
}
__device__ __forceinline__ void ldm4(uint32_t* r, uint32_t addr) {
    asm volatile("ldmatrix.sync.aligned.m8n8.x4.shared.b16 {%0,%1,%2,%3}, [%4];"
                 : "=r"(r[0]), "=r"(r[1]), "=r"(r[2]), "=r"(r[3]) : "r"(addr));
}
__device__ __forceinline__ void mma16816(float* c, const uint32_t* a, const uint32_t* b) {
    asm volatile(
        "mma.sync.aligned.m16n8k16.row.col.f32.bf16.bf16.f32 "
        "{%0,%1,%2,%3}, {%4,%5,%6,%7}, {%8,%9}, {%0,%1,%2,%3};"
        : "+f"(c[0]), "+f"(c[1]), "+f"(c[2]), "+f"(c[3])
        : "r"(a[0]), "r"(a[1]), "r"(a[2]), "r"(a[3]), "r"(b[0]), "r"(b[1]));
}
__device__ __forceinline__ void st_cs32(void* p, uint32_t v) {
    asm volatile("st.global.cs.b32 [%0], %1;" :: "l"(p), "r"(v) : "memory");
}

// ---------------------------------------------------------------------------
__global__ void k_zero() {
    int i = blockIdx.x * 256 + threadIdx.x;       // grid covers 2097152
    if (i < VCODES * DDIM) g_encsum[i] = 0.0f;
    if (i < MROWS)  g_best[i] = 0ull;
    if (i < VCODES) g_counts[i] = 0.0f;
    if (i == 0) { g_sumN = 0.0f; g_qd = 0.0f; }
}

// x (b, D=k, s) -> g_abf[r=b*4096+s][k] bf16
__global__ void k_prep_x(const float* __restrict__ x) {
    __shared__ float t[32][33];
    int k0 = blockIdx.x * 32, s0 = blockIdx.y * 32, b = blockIdx.z;
    int tx = threadIdx.x, ty = threadIdx.y;       // (32, 8)
#pragma unroll
    for (int i = 0; i < 4; ++i)
        t[ty + i * 8][tx] = x[(size_t)b * 1048576 + (size_t)(k0 + ty + i * 8) * SPAT + s0 + tx];
    __syncthreads();
#pragma unroll
    for (int i = 0; i < 4; ++i) {
        int r = b * SPAT + s0 + ty + i * 8;
        g_abf[(size_t)r * DDIM + k0 + tx] = __float2bfloat16(t[tx][ty + i * 8]);
    }
}

// weight -> bf16; wsq per code; sum(N)
__global__ void k_prep_w(const float* __restrict__ w, const float* __restrict__ N) {
    int gid  = blockIdx.x * 256 + threadIdx.x;
    int v = gid >> 5, lane = gid & 31;
    const float* row = w + (size_t)v * DDIM;
    float s = 0.0f;
#pragma unroll
    for (int t = lane; t < DDIM; t += 32) {
        float a = row[t];
        s += a * a;
        g_wbf[(size_t)v * DDIM + t] = __float2bfloat16(a);
    }
#pragma unroll
    for (int o = 16; o; o >>= 1) s += __shfl_xor_sync(0xFFFFFFFFu, s, o);
    if (lane == 0) {
        g_wsq[v] = s;
        atomicAdd(&g_sumN, N[v]);
    }
}

// ---------------------------------------------------------------------------
// bf16 HMMA GEMM: CTA 128m x 256n, 8 warps of 64x64 (smem-port ratio 0.06
// B/MAC vs 0.09 at 64x32 -> port no longer binds). 1 CTA/SM, 192KB smem:
// both K-half stages prefetched up front, 2 barriers total.
// 256B rows, 16B-chunk swizzle c ^= row&7.
#define STAGE_B 98304     // A 32KB + B 64KB
#define SMEM_DYN (2 * STAGE_B)

__global__ __launch_bounds__(256, 1) void k_gemm() {
    extern __shared__ __align__(16) char sm[];
    const int tid = threadIdx.x;
    const int lane = tid & 31, wid = tid >> 5;
    const int wm = wid & 1, wn = wid >> 1;        // 2m x 4n grid, 64x64 tiles
    const int jbase = blockIdx.x * 256;
    const int rbase = blockIdx.y * 128;
    const uint32_t smb = smem_u32(sm);

    const int sel = lane >> 3, rin = lane & 7;

    // fragment row bases + swizzle (A rows at 0, B rows at 32768 within stage)
    uint32_t baseA[4]; int vA[4];
#pragma unroll
    for (int i = 0; i < 4; ++i) {
        int row = wm * 64 + i * 16 + rin + ((sel & 1) << 3);
        baseA[i] = (uint32_t)(row * 256);
        vA[i] = row & 7;
    }
    const int hA = sel >> 1;
    uint32_t baseB[4]; int vB[4];
#pragma unroll
    for (int p = 0; p < 4; ++p) {
        int row = wn * 64 + p * 16 + rin + ((sel >> 1) << 3);
        baseB[p] = (uint32_t)(32768 + row * 256);
        vB[p] = row & 7;
    }
    const int hB = sel & 1;

    // prefetch BOTH K-halves up front (cp.async), one commit per stage
#pragma unroll
    for (int r = 0; r < 2; ++r) {
        uint32_t sb = smb + r * STAGE_B;
#pragma unroll
        for (int e = 0; e < 24; ++e) {
            int idx = tid + e * 256;              // 0..6143
            if (idx < 2048) {                     // A: 128 rows x 16 chunks
                int row = idx >> 4, c = idx & 15;
                uint32_t sw = (uint32_t)((c ^ (row & 7)) << 4);
                cp16(sb + row * 256 + sw,
                     g_abf + (size_t)(rbase + row) * DDIM + r * 128 + c * 8);
            } else {                              // B: 256 rows x 16 chunks
                int ib = idx - 2048;
                int row = ib >> 4, c = ib & 15;
                uint32_t sw = (uint32_t)((c ^ (row & 7)) << 4);
                cp16(sb + 32768 + row * 256 + sw,
                     g_wbf + (size_t)(jbase + row) * DDIM + r * 128 + c * 8);
            }
        }
        asm volatile("cp.async.commit_group;" ::: "memory");
    }

    float acc[4][8][4];
#pragma unroll
    for (int i = 0; i < 4; ++i)
#pragma unroll
        for (int j = 0; j < 8; ++j)
#pragma unroll
            for (int q = 0; q < 4; ++q) acc[i][j][q] = 0.0f;

#pragma unroll
    for (int r = 0; r < 2; ++r) {
        if (r == 0) asm volatile("cp.async.wait_group 1;" ::: "memory");
        else        asm volatile("cp.async.wait_group 0;" ::: "memory");
        __syncthreads();
        uint32_t sb = smb + r * STAGE_B;
#pragma unroll
        for (int ks = 0; ks < 8; ++ks) {
            uint32_t a[4][4], bf[8][2];
#pragma unroll
            for (int i = 0; i < 4; ++i)
                ldm4(a[i], sb + baseA[i] + (((2 * ks + hA) ^ vA[i]) << 4));
#pragma unroll
            for (int p = 0; p < 4; ++p) {
                uint32_t r4[4];
                ldm4(r4, sb + baseB[p] + (((2 * ks + hB) ^ vB[p]) << 4));
                bf[2 * p][0] = r4[0]; bf[2 * p][1] = r4[1];
                bf[2 * p + 1][0] = r4[2]; bf[2 * p + 1][1] = r4[3];
            }
#pragma unroll
            for (int i = 0; i < 4; ++i)
#pragma unroll
                for (int j = 0; j < 8; ++j)
                    mma16816(acc[i][j], a[i], bf[j]);
        }
    }

    // epilogue: scores = acc - 0.5*wsq; store bf16 (streaming); per-row argmax
    const int lq = lane >> 2, lr = lane & 3;
    float bv[8]; int bj[8];
#pragma unroll
    for (int s = 0; s < 8; ++s) { bv[s] = -3.4e38f; bj[s] = 0; }

#pragma unroll
    for (int j = 0; j < 8; ++j) {
        int col = jbase + wn * 64 + j * 8 + lr * 2;
        float2 wq = *reinterpret_cast<const float2*>(&g_wsq[col]);
#pragma unroll
        for (int i = 0; i < 4; ++i) {
#pragma unroll
            for (int h = 0; h < 2; ++h) {
                float s0 = acc[i][j][h * 2 + 0] - 0.5f * wq.x;
                float s1 = acc[i][j][h * 2 + 1] - 0.5f * wq.y;
                int grow = rbase + wm * 64 + i * 16 + lq + h * 8;
                __nv_bfloat162 pr = __floats2bfloat162_rn(s0, s1);
                st_cs32(&g_scores[(size_t)grow * VCODES + col],
                        *reinterpret_cast<uint32_t*>(&pr));
                int slot = i * 2 + h;
                if (s0 > bv[slot]) { bv[slot] = s0; bj[slot] = col; }
                if (s1 > bv[slot]) { bv[slot] = s1; bj[slot] = col + 1; }
            }
        }
    }
#pragma unroll
    for (int s = 0; s < 8; ++s) {
        unsigned u = __float_as_uint(bv[s]);
        u = (u & 0x80000000u) ? ~u : (u | 0x80000000u);
        unsigned long long key = ((unsigned long long)u << 32) |
                                 (unsigned)(0xFFFFFFFFu - (unsigned)bj[s]);
#pragma unroll
        for (int o = 1; o < 4; o <<= 1) {
            unsigned long long v = __shfl_xor_sync(0xFFFFFFFFu, key, o);
            if (v > key) key = v;
        }
        if (lr == 0) {
            int grow = rbase + wm * 64 + (s >> 1) * 16 + lq + (s & 1) * 8;
            atomicMax(&g_best[grow], key);
        }
    }
}

// ---------------------------------------------------------------------------
// Repair: per-row warp rescans bf16 scores (streaming loads), exact fp32
// recompute of candidates within MARGIN of the coarse winner.
__global__ void k_repair(const float* __restrict__ x, const float* __restrict__ w,
                         float* __restrict__ out) {
    int r = blockIdx.x * 8 + (threadIdx.x >> 5);
    int lane = threadIdx.x & 31;
    unsigned long long kk = g_best[r];
    unsigned u = (unsigned)(kk >> 32);
    unsigned bits = (u & 0x80000000u) ? (u & 0x7FFFFFFFu) : ~u;
    float thr = __uint_as_float(bits) - MARGIN;
    int b = r >> 12, s = r & 4095;
    const float* xb = x + (size_t)b * 1048576 + s;
    float bestv = -3.4e38f;
    int   bestj = 0;
    const uint4* rowp = reinterpret_cast<const uint4*>(g_scores + (size_t)r * VCODES);
#pragma unroll 1
    for (int it = 0; it < 32; ++it) {
        uint4 v = __ldcs(rowp + it * 32 + lane);
        unsigned m = 0;
        unsigned wds[4] = {v.x, v.y, v.z, v.w};
#pragma unroll
        for (int q = 0; q < 4; ++q) {
            __nv_bfloat162 h2 = *reinterpret_cast<__nv_bfloat162*>(&wds[q]);
            float2 f = __bfloat1622float2(h2);
            if (f.x >= thr) m |= 1u << (2 * q);
            if (f.y >= thr) m |= 1u << (2 * q + 1);
        }
        unsigned act = __ballot_sync(0xFFFFFFFFu, m != 0);
        while (act) {
            int src = __ffs(act) - 1; act &= act - 1;
            unsigned mm = __shfl_sync(0xFFFFFFFFu, m, src);
            while (mm) {
                int bit = __ffs(mm) - 1; mm &= mm - 1;
                int j = it * 256 + src * 8 + bit;
                const float* wr = w + (size_t)j * DDIM;
                float p = 0.0f;
#pragma unroll
                for (int q = 0; q < 8; ++q) {
                    int k = lane + q * 32;
                    p += xb[(size_t)k * SPAT] * wr[k];
                }
#pragma unroll
                for (int o = 16; o; o >>= 1) p += __shfl_xor_sync(0xFFFFFFFFu, p, o);
                float sc = p - 0.5f * g_wsq[j];
                if (sc > bestv) { bestv = sc; bestj = j; }   // ascending j -> first-idx tie-break
            }
        }
    }
    if (lane == 0) {
        g_idx[r] = bestj;
        out[O_IDX + r] = (float)bestj;
        atomicAdd(&g_counts[bestj], 1.0f);
    }
}

// ---------------------------------------------------------------------------
// quant write (coalesced over spatial), enc_sum atomics, quant_diff
__global__ void k_assign(const float* __restrict__ x, const float* __restrict__ w,
                         float* __restrict__ out) {
    __shared__ int sidx[128];
    __shared__ float red[8];
    int bi = blockIdx.x;
    int b = bi >> 5, s0 = (bi & 31) * 128;
    int tid = threadIdx.x, ts = tid & 127, dg = tid >> 7;
    if (tid < 128) sidx[tid] = g_idx[b * SPAT + s0 + tid];
    __syncthreads();
    int j = sidx[ts];
    const float* wr = w + (size_t)j * DDIM;
    float* er = g_encsum + (size_t)j * DDIM;
    size_t basex = (size_t)b * 1048576 + s0 + ts;
    float qd = 0.0f;
#pragma unroll 4
    for (int d = dg; d < 256; d += 2) {
        size_t off = basex + (size_t)d * SPAT;
        float xv = x[off];
        float wv = __ldg(wr + d);
        out[O_QUANT + off] = (wv - xv) + xv;
        float df = xv - wv;
        qd += df * df;
        atomicAdd(er + d, xv);
    }
#pragma unroll
    for (int o = 16; o; o >>= 1) qd += __shfl_xor_sync(0xFFFFFFFFu, qd, o);
    if ((tid & 31) == 0) red[tid >> 5] = qd;
    __syncthreads();
    if (tid == 0) {
        float t = 0.0f;
#pragma unroll
        for (int i = 0; i < 8; ++i) t += red[i];
        atomicAdd(&g_qd, t);
    }
}

// ---------------------------------------------------------------------------
__global__ void k_update(const float* __restrict__ N, const float* __restrict__ z_avg,
                         float* __restrict__ out) {
    int i = blockIdx.x * 256 + threadIdx.x;
    if (i >= VCODES * DDIM) return;
    int v = i >> 8, d = i & 255;
    float gamma = 0.99f, om = 0.01f, eps = 1e-7f;
    float n  = gamma * g_sumN + om * (float)MROWS;
    float nN = gamma * N[v] + om * g_counts[v];
    float wgt = (nN + eps) / (n + (float)VCODES * eps) * n;
    float za = gamma * z_avg[i] + om * g_encsum[i];
    out[O_ZAVG + i] = za;
    out[O_NEWW + i] = za / wgt;
    if (d == 0) out[O_NEWN + v] = nN;
    if (i == 0) out[O_QD] = g_qd * (1.0f / 8388608.0f);
}

// ---------------------------------------------------------------------------
extern "C" void kernel_launch(void* const* d_in, const int* in_sizes, int n_in,
                              void* d_out, int out_size) {
    const float* x    = (const float*)d_in[0];
    const float* w    = (const float*)d_in[1];
    const float* N    = (const float*)d_in[2];
    const float* zavg = (const float*)d_in[3];
    float* out = (float*)d_out;

    cudaFuncSetAttribute(k_gemm, cudaFuncAttributeMaxDynamicSharedMemorySize, SMEM_DYN);

    k_zero<<<8192, 256>>>();
    k_prep_x<<<dim3(8, 128, 8), dim3(32, 8)>>>(x);
    k_prep_w<<<1024, 256>>>(w, N);
    k_gemm<<<dim3(VCODES / 256, MROWS / 128), 256, SMEM_DYN>>>();
    k_repair<<<MROWS / 8, 256>>>(x, w, out);
    k_assign<<<256, 256>>>(x, w, out);
    k_update<<<VCODES * DDIM / 256, 256>>>(N, zavg, out);
}

// round 12
// speedup vs baseline: 1.0864x; 1.0864x over previous
#include <cuda_runtime.h>
#include <cuda_bf16.h>
#include <cuda_fp16.h>
#include <cstdint>

// Problem constants
#define VCODES 8192
#define DDIM   256
#define MROWS  32768      // 8 * 16*16*16
#define SPAT   4096       // 16*16*16

// Output layout (concatenated f32)
#define O_QUANT 0ul
#define O_IDX   8388608ul
#define O_QD    8421376ul
#define O_NEWN  8421377ul
#define O_ZAVG  8429569ul
#define O_NEWW  10526721ul

#define MARGIN 3.0f

// ---------------------------------------------------------------------------
// Scratch (device globals; no allocations allowed)
__device__ unsigned long long g_best[MROWS];
__device__ int   g_idx[MROWS];
__device__ float g_counts[VCODES];
__device__ float g_encsum[VCODES * DDIM];
__device__ float g_wsq[VCODES];
__device__ float g_sumN;
__device__ float g_qd;
__device__ __half g_ahf[MROWS * DDIM];           // flat x, fp16
__device__ __half g_whf[VCODES * DDIM];          // weight, fp16
__device__ __nv_bfloat16 g_scores[(size_t)MROWS * VCODES];  // coarse scores

// ---------------------------------------------------------------------------
__device__ __forceinline__ uint32_t smem_u32(const void* p) {
    uint32_t a;
    asm("{ .reg .u64 t; cvta.to.shared.u64 t, %1; cvt.u32.u64 %0, t; }" : "=r"(a) : "l"(p));
    return a;
}
__device__ __forceinline__ void cp16(uint32_t dst, const void* src) {
    asm volatile("cp.async.cg.shared.global [%0], [%1], 16;" :: "r"(dst), "l"(src) : "memory");
}
__device__ __forceinline__ void ldm4(uint32_t* r, uint32_t addr) {
    asm volatile("ldmatrix.sync.aligned.m8n8.x4.shared.b16 {%0,%1,%2,%3}, [%4];"
                 : "=r"(r[0]), "=r"(r[1]), "=r"(r[2]), "=r"(r[3]) : "r"(addr));
}
// fp16-accumulate HMMA: D(f16x2 x2) = A(f16) * B(f16) + C
__device__ __forceinline__ void mma16816h(uint32_t* c, const uint32_t* a, const uint32_t* b) {
    asm volatile(
        "mma.sync.aligned.m16n8k16.row.col.f16.f16.f16.f16 "
        "{%0,%1}, {%2,%3,%4,%5}, {%6,%7}, {%0,%1};"
        : "+r"(c[0]), "+r"(c[1])
        : "r"(a[0]), "r"(a[1]), "r"(a[2]), "r"(a[3]), "r"(b[0]), "r"(b[1]));
}
__device__ __forceinline__ void st_cs32(void* p, uint32_t v) {
    asm volatile("st.global.cs.b32 [%0], %1;" :: "l"(p), "r"(v) : "memory");
}

// ---------------------------------------------------------------------------
__global__ void k_zero() {
    int i = blockIdx.x * 256 + threadIdx.x;       // grid covers 2097152
    if (i < VCODES * DDIM) g_encsum[i] = 0.0f;
    if (i < MROWS)  g_best[i] = 0ull;
    if (i < VCODES) g_counts[i] = 0.0f;
    if (i == 0) { g_sumN = 0.0f; g_qd = 0.0f; }
}

// x (b, D=k, s) -> g_ahf[r=b*4096+s][k] fp16
__global__ void k_prep_x(const float* __restrict__ x) {
    __shared__ float t[32][33];
    int k0 = blockIdx.x * 32, s0 = blockIdx.y * 32, b = blockIdx.z;
    int tx = threadIdx.x, ty = threadIdx.y;       // (32, 8)
#pragma unroll
    for (int i = 0; i < 4; ++i)
        t[ty + i * 8][tx] = x[(size_t)b * 1048576 + (size_t)(k0 + ty + i * 8) * SPAT + s0 + tx];
    __syncthreads();
#pragma unroll
    for (int i = 0; i < 4; ++i) {
        int r = b * SPAT + s0 + ty + i * 8;
        g_ahf[(size_t)r * DDIM + k0 + tx] = __float2half_rn(t[tx][ty + i * 8]);
    }
}

// weight -> fp16; wsq per code; sum(N)
__global__ void k_prep_w(const float* __restrict__ w, const float* __restrict__ N) {
    int gid  = blockIdx.x * 256 + threadIdx.x;
    int v = gid >> 5, lane = gid & 31;
    const float* row = w + (size_t)v * DDIM;
    float s = 0.0f;
#pragma unroll
    for (int t = lane; t < DDIM; t += 32) {
        float a = row[t];
        s += a * a;
        g_whf[(size_t)v * DDIM + t] = __float2half_rn(a);
    }
#pragma unroll
    for (int o = 16; o; o >>= 1) s += __shfl_xor_sync(0xFFFFFFFFu, s, o);
    if (lane == 0) {
        g_wsq[v] = s;
        atomicAdd(&g_sumN, N[v]);
    }
}

// ---------------------------------------------------------------------------
// fp16-accum HMMA GEMM (full-rate path): CTA 128x128, 8 warps of 64x32,
// K-chunk=64, 3-stage x 32KB pipeline in 96KB dyn smem, 128B rows,
// c^=(row&7) swizzle (R8 structure, types swapped).
#define STAGE_B 32768
#define SMEM_DYN (3 * STAGE_B)

__global__ __launch_bounds__(256, 2) void k_gemm() {
    extern __shared__ __align__(16) char sm[];
    const int tid = threadIdx.x;
    const int lane = tid & 31, wid = tid >> 5;
    const int wm = wid & 1, wn = wid >> 1;        // warp tile 64m x 32n
    const int jbase = blockIdx.x * 128;
    const int rbase = blockIdx.y * 128;
    const uint32_t smb = smem_u32(sm);

    const int sel = lane >> 3, rin = lane & 7;

    uint32_t baseA[4]; int vA[4];
#pragma unroll
    for (int i = 0; i < 4; ++i) {
        int row = wm * 64 + i * 16 + rin + ((sel & 1) << 3);
        baseA[i] = (uint32_t)(row * 128);
        vA[i] = row & 7;
    }
    const int hA = sel >> 1;
    uint32_t baseB[2]; int vB[2];
#pragma unroll
    for (int p = 0; p < 2; ++p) {
        int row = wn * 32 + p * 16 + rin + ((sel >> 1) << 3);
        baseB[p] = (uint32_t)(16384 + row * 128);
        vB[p] = row & 7;
    }
    const int hB = sel & 1;

    // cp.async: 8 x 16B per thread per stage (A: e 0..3, B: e 4..7)
    const __half* sp[8];
    uint32_t doff[8];
#pragma unroll
    for (int e = 0; e < 8; ++e) {
        int idx = tid + (e & 3) * 256;             // 0..1023
        int row = idx >> 3, c = idx & 7;
        if (e < 4) {
            sp[e] = g_ahf + (size_t)(rbase + row) * DDIM + c * 8;
            doff[e] = (uint32_t)(row * 128 + ((c ^ (row & 7)) << 4));
        } else {
            sp[e] = g_whf + (size_t)(jbase + row) * DDIM + c * 8;
            doff[e] = (uint32_t)(16384 + row * 128 + ((c ^ (row & 7)) << 4));
        }
    }

    uint32_t acc[4][4][2];
#pragma unroll
    for (int i = 0; i < 4; ++i)
#pragma unroll
        for (int j = 0; j < 4; ++j) { acc[i][j][0] = 0u; acc[i][j][1] = 0u; }

#define LOAD_STAGE(st, ko)                                                \
    do {                                                                  \
        uint32_t sb_ = smb + (st) * STAGE_B;                              \
        _Pragma("unroll")                                                 \
        for (int e = 0; e < 8; ++e) cp16(sb_ + doff[e], sp[e] + (ko));    \
        asm volatile("cp.async.commit_group;" ::: "memory");              \
    } while (0)

    LOAD_STAGE(0, 0);
    LOAD_STAGE(1, 64);

#pragma unroll
    for (int c = 0; c < 4; ++c) {
        if (c < 3) asm volatile("cp.async.wait_group 1;" ::: "memory");
        else       asm volatile("cp.async.wait_group 0;" ::: "memory");
        __syncthreads();
        if (c < 2) LOAD_STAGE(c + 2 - ((c + 2 >= 3) ? 3 : 0), (c + 2) * 64);
        uint32_t sb = smb + (c % 3) * STAGE_B;
#pragma unroll
        for (int ks = 0; ks < 4; ++ks) {          // 4 x K16 per chunk
            uint32_t a[4][4], bf[4][2];
#pragma unroll
            for (int i = 0; i < 4; ++i)
                ldm4(a[i], sb + baseA[i] + (((ks * 2 + hA) ^ vA[i]) << 4));
#pragma unroll
            for (int p = 0; p < 2; ++p) {
                uint32_t r4[4];
                ldm4(r4, sb + baseB[p] + (((ks * 2 + hB) ^ vB[p]) << 4));
                bf[2 * p][0] = r4[0]; bf[2 * p][1] = r4[1];
                bf[2 * p + 1][0] = r4[2]; bf[2 * p + 1][1] = r4[3];
            }
#pragma unroll
            for (int i = 0; i < 4; ++i)
#pragma unroll
                for (int j = 0; j < 4; ++j)
                    mma16816h(acc[i][j], a[i], bf[j]);
        }
    }
#undef LOAD_STAGE

    // epilogue: unpack fp16 acc; scores = acc - 0.5*wsq; store bf16; argmax
    const int lq = lane >> 2, lr = lane & 3;
    float bv[8]; int bj[8];
#pragma unroll
    for (int s = 0; s < 8; ++s) { bv[s] = -3.4e38f; bj[s] = 0; }

#pragma unroll
    for (int j = 0; j < 4; ++j) {
        int col = jbase + wn * 32 + j * 8 + lr * 2;
        float2 wq = *reinterpret_cast<const float2*>(&g_wsq[col]);
#pragma unroll
        for (int i = 0; i < 4; ++i) {
#pragma unroll
            for (int h = 0; h < 2; ++h) {
                float2 f = __half22float2(*reinterpret_cast<__half2*>(&acc[i][j][h]));
                float s0 = f.x - 0.5f * wq.x;
                float s1 = f.y - 0.5f * wq.y;
                int grow = rbase + wm * 64 + i * 16 + lq + h * 8;
                __nv_bfloat162 pr = __floats2bfloat162_rn(s0, s1);
                st_cs32(&g_scores[(size_t)grow * VCODES + col],
                        *reinterpret_cast<uint32_t*>(&pr));
                int slot = i * 2 + h;
                if (s0 > bv[slot]) { bv[slot] = s0; bj[slot] = col; }
                if (s1 > bv[slot]) { bv[slot] = s1; bj[slot] = col + 1; }
            }
        }
    }
#pragma unroll
    for (int s = 0; s < 8; ++s) {
        unsigned u = __float_as_uint(bv[s]);
        u = (u & 0x80000000u) ? ~u : (u | 0x80000000u);
        unsigned long long key = ((unsigned long long)u << 32) |
                                 (unsigned)(0xFFFFFFFFu - (unsigned)bj[s]);
#pragma unroll
        for (int o = 1; o < 4; o <<= 1) {
            unsigned long long v = __shfl_xor_sync(0xFFFFFFFFu, key, o);
            if (v > key) key = v;
        }
        if (lr == 0) {
            int grow = rbase + wm * 64 + (s >> 1) * 16 + lq + (s & 1) * 8;
            atomicMax(&g_best[grow], key);
        }
    }
}

// ---------------------------------------------------------------------------
// Repair: per-row warp rescans bf16 scores (streaming loads), exact fp32
// recompute of candidates within MARGIN of the coarse winner.
__global__ void k_repair(const float* __restrict__ x, const float* __restrict__ w,
                         float* __restrict__ out) {
    int r = blockIdx.x * 8 + (threadIdx.x >> 5);
    int lane = threadIdx.x & 31;
    unsigned long long kk = g_best[r];
    unsigned u = (unsigned)(kk >> 32);
    unsigned bits = (u & 0x80000000u) ? (u & 0x7FFFFFFFu) : ~u;
    float thr = __uint_as_float(bits) - MARGIN;
    int b = r >> 12, s = r & 4095;
    const float* xb = x + (size_t)b * 1048576 + s;
    float bestv = -3.4e38f;
    int   bestj = 0;
    const uint4* rowp = reinterpret_cast<const uint4*>(g_scores + (size_t)r * VCODES);
#pragma unroll 1
    for (int it = 0; it < 32; ++it) {
        uint4 v = __ldcs(rowp + it * 32 + lane);
        unsigned m = 0;
        unsigned wds[4] = {v.x, v.y, v.z, v.w};
#pragma unroll
        for (int q = 0; q < 4; ++q) {
            __nv_bfloat162 h2 = *reinterpret_cast<__nv_bfloat162*>(&wds[q]);
            float2 f = __bfloat1622float2(h2);
            if (f.x >= thr) m |= 1u << (2 * q);
            if (f.y >= thr) m |= 1u << (2 * q + 1);
        }
        unsigned act = __ballot_sync(0xFFFFFFFFu, m != 0);
        while (act) {
            int src = __ffs(act) - 1; act &= act - 1;
            unsigned mm = __shfl_sync(0xFFFFFFFFu, m, src);
            while (mm) {
                int bit = __ffs(mm) - 1; mm &= mm - 1;
                int j = it * 256 + src * 8 + bit;
                const float* wr = w + (size_t)j * DDIM;
                float p = 0.0f;
#pragma unroll
                for (int q = 0; q < 8; ++q) {
                    int k = lane + q * 32;
                    p += xb[(size_t)k * SPAT] * wr[k];
                }
#pragma unroll
                for (int o = 16; o; o >>= 1) p += __shfl_xor_sync(0xFFFFFFFFu, p, o);
                float sc = p - 0.5f * g_wsq[j];
                if (sc > bestv) { bestv = sc; bestj = j; }   // ascending j -> first-idx tie-break
            }
        }
    }
    if (lane == 0) {
        g_idx[r] = bestj;
        out[O_IDX + r] = (float)bestj;
        atomicAdd(&g_counts[bestj], 1.0f);
    }
}

// ---------------------------------------------------------------------------
// quant write (coalesced over spatial), enc_sum atomics, quant_diff
__global__ void k_assign(const float* __restrict__ x, const float* __restrict__ w,
                         float* __restrict__ out) {
    __shared__ int sidx[128];
    __shared__ float red[8];
    int bi = blockIdx.x;
    int b = bi >> 5, s0 = (bi & 31) * 128;
    int tid = threadIdx.x, ts = tid & 127, dg = tid >> 7;
    if (tid < 128) sidx[tid] = g_idx[b * SPAT + s0 + tid];
    __syncthreads();
    int j = sidx[ts];
    const float* wr = w + (size_t)j * DDIM;
    float* er = g_encsum + (size_t)j * DDIM;
    size_t basex = (size_t)b * 1048576 + s0 + ts;
    float qd = 0.0f;
#pragma unroll 4
    for (int d = dg; d < 256; d += 2) {
        size_t off = basex + (size_t)d * SPAT;
        float xv = x[off];
        float wv = __ldg(wr + d);
        out[O_QUANT + off] = (wv - xv) + xv;
        float df = xv - wv;
        qd += df * df;
        atomicAdd(er + d, xv);
    }
#pragma unroll
    for (int o = 16; o; o >>= 1) qd += __shfl_xor_sync(0xFFFFFFFFu, qd, o);
    if ((tid & 31) == 0) red[tid >> 5] = qd;
    __syncthreads();
    if (tid == 0) {
        float t = 0.0f;
#pragma unroll
        for (int i = 0; i < 8; ++i) t += red[i];
        atomicAdd(&g_qd, t);
    }
}

// ---------------------------------------------------------------------------
__global__ void k_update(const float* __restrict__ N, const float* __restrict__ z_avg,
                         float* __restrict__ out) {
    int i = blockIdx.x * 256 + threadIdx.x;
    if (i >= VCODES * DDIM) return;
    int v = i >> 8, d = i & 255;
    float gamma = 0.99f, om = 0.01f, eps = 1e-7f;
    float n  = gamma * g_sumN + om * (float)MROWS;
    float nN = gamma * N[v] + om * g_counts[v];
    float wgt = (nN + eps) / (n + (float)VCODES * eps) * n;
    float za = gamma * z_avg[i] + om * g_encsum[i];
    out[O_ZAVG + i] = za;
    out[O_NEWW + i] = za / wgt;
    if (d == 0) out[O_NEWN + v] = nN;
    if (i == 0) out[O_QD] = g_qd * (1.0f / 8388608.0f);
}

// ---------------------------------------------------------------------------
extern "C" void kernel_launch(void* const* d_in, const int* in_sizes, int n_in,
                              void* d_out, int out_size) {
    const float* x    = (const float*)d_in[0];
    const float* w    = (const float*)d_in[1];
    const float* N    = (const float*)d_in[2];
    const float* zavg = (const float*)d_in[3];
    float* out = (float*)d_out;

    cudaFuncSetAttribute(k_gemm, cudaFuncAttributeMaxDynamicSharedMemorySize, SMEM_DYN);

    k_zero<<<8192, 256>>>();
    k_prep_x<<<dim3(8, 128, 8), dim3(32, 8)>>>(x);
    k_prep_w<<<1024, 256>>>(w, N);
    k_gemm<<<dim3(VCODES / 128, MROWS / 128), 256, SMEM_DYN>>>();
    k_repair<<<MROWS / 8, 256>>>(x, w, out);
    k_assign<<<256, 256>>>(x, w, out);
    k_update<<<VCODES * DDIM / 256, 256>>>(N, zavg, out);
}

// round 13
// speedup vs baseline: 1.1482x; 1.0569x over previous
#include <cuda_runtime.h>
#include <cuda_bf16.h>
#include <cuda_fp16.h>
#include <cstdint>

// Problem constants
#define VCODES 8192
#define DDIM   256
#define MROWS  32768      // 8 * 16*16*16
#define SPAT   4096       // 16*16*16
#define NTILES 64         // VCODES / 128

// Output layout (concatenated f32)
#define O_QUANT 0ul
#define O_IDX   8388608ul
#define O_QD    8421376ul
#define O_NEWN  8421377ul
#define O_ZAVG  8429569ul
#define O_NEWW  10526721ul

#define MARGIN 3.0f

// ---------------------------------------------------------------------------
// Scratch (device globals; no allocations allowed)
__device__ unsigned long long g_best[MROWS];
__device__ int   g_idx[MROWS];
__device__ float g_counts[VCODES];
__device__ float g_encsum[VCODES * DDIM];
__device__ float g_wsq[VCODES];
__device__ float g_sumN;
__device__ float g_qd;
__device__ unsigned g_tilemax[MROWS * NTILES];   // monotone-encoded fp32 max per (row, tile)
__device__ __half g_ahf[MROWS * DDIM];           // flat x, fp16
__device__ __half g_whf[VCODES * DDIM];          // weight, fp16
__device__ __nv_bfloat16 g_scores[(size_t)MROWS * VCODES];  // coarse scores

// ---------------------------------------------------------------------------
__device__ __forceinline__ uint32_t smem_u32(const void* p) {
    uint32_t a;
    asm("{ .reg .u64 t; cvta.to.shared.u64 t, %1; cvt.u32.u64 %0, t; }" : "=r"(a) : "l"(p));
    return a;
}
__device__ __forceinline__ void cp16(uint32_t dst, const void* src) {
    asm volatile("cp.async.cg.shared.global [%0], [%1], 16;" :: "r"(dst), "l"(src) : "memory");
}
__device__ __forceinline__ void ldm4(uint32_t* r, uint32_t addr) {
    asm volatile("ldmatrix.sync.aligned.m8n8.x4.shared.b16 {%0,%1,%2,%3}, [%4];"
                 : "=r"(r[0]), "=r"(r[1]), "=r"(r[2]), "=r"(r[3]) : "r"(addr));
}
// fp16-accumulate HMMA: D(f16x2 x2) = A(f16) * B(f16) + C
__device__ __forceinline__ void mma16816h(uint32_t* c, const uint32_t* a, const uint32_t* b) {
    asm volatile(
        "mma.sync.aligned.m16n8k16.row.col.f16.f16.f16.f16 "
        "{%0,%1}, {%2,%3,%4,%5}, {%6,%7}, {%0,%1};"
        : "+r"(c[0]), "+r"(c[1])
        : "r"(a[0]), "r"(a[1]), "r"(a[2]), "r"(a[3]), "r"(b[0]), "r"(b[1]));
}
__device__ __forceinline__ void st_cs32(void* p, uint32_t v) {
    asm volatile("st.global.cs.b32 [%0], %1;" :: "l"(p), "r"(v) : "memory");
}
__device__ __forceinline__ unsigned enc_f(float f) {
    unsigned u = __float_as_uint(f);
    return (u & 0x80000000u) ? ~u : (u | 0x80000000u);
}
__device__ __forceinline__ float dec_f(unsigned u) {
    unsigned b = (u & 0x80000000u) ? (u & 0x7FFFFFFFu) : ~u;
    return __uint_as_float(b);
}

// ---------------------------------------------------------------------------
__global__ void k_zero() {
    int i = blockIdx.x * 256 + threadIdx.x;       // grid covers 2097152
    if (i < VCODES * DDIM) g_encsum[i] = 0.0f;
    if (i < MROWS * NTILES) g_tilemax[i] = 0u;    // decodes to large negative
    if (i < MROWS)  g_best[i] = 0ull;
    if (i < VCODES) g_counts[i] = 0.0f;
    if (i == 0) { g_sumN = 0.0f; g_qd = 0.0f; }
}

// x (b, D=k, s) -> g_ahf[r=b*4096+s][k] fp16
__global__ void k_prep_x(const float* __restrict__ x) {
    __shared__ float t[32][33];
    int k0 = blockIdx.x * 32, s0 = blockIdx.y * 32, b = blockIdx.z;
    int tx = threadIdx.x, ty = threadIdx.y;       // (32, 8)
#pragma unroll
    for (int i = 0; i < 4; ++i)
        t[ty + i * 8][tx] = x[(size_t)b * 1048576 + (size_t)(k0 + ty + i * 8) * SPAT + s0 + tx];
    __syncthreads();
#pragma unroll
    for (int i = 0; i < 4; ++i) {
        int r = b * SPAT + s0 + ty + i * 8;
        g_ahf[(size_t)r * DDIM + k0 + tx] = __float2half_rn(t[tx][ty + i * 8]);
    }
}

// weight -> fp16; wsq per code; sum(N)
__global__ void k_prep_w(const float* __restrict__ w, const float* __restrict__ N) {
    int gid  = blockIdx.x * 256 + threadIdx.x;
    int v = gid >> 5, lane = gid & 31;
    const float* row = w + (size_t)v * DDIM;
    float s = 0.0f;
#pragma unroll
    for (int t = lane; t < DDIM; t += 32) {
        float a = row[t];
        s += a * a;
        g_whf[(size_t)v * DDIM + t] = __float2half_rn(a);
    }
#pragma unroll
    for (int o = 16; o; o >>= 1) s += __shfl_xor_sync(0xFFFFFFFFu, s, o);
    if (lane == 0) {
        g_wsq[v] = s;
        atomicAdd(&g_sumN, N[v]);
    }
}

// ---------------------------------------------------------------------------
// fp16-accum HMMA GEMM: CTA 128x128, 8 warps of 64x32, K-chunk=64, 3-stage
// x 32KB pipeline, 96KB dyn smem, 128B rows, c^=(row&7) swizzle.
// Epilogue also maintains g_tilemax for tile-guided repair.
#define STAGE_B 32768
#define SMEM_DYN (3 * STAGE_B)

__global__ __launch_bounds__(256, 2) void k_gemm() {
    extern __shared__ __align__(16) char sm[];
    const int tid = threadIdx.x;
    const int lane = tid & 31, wid = tid >> 5;
    const int wm = wid & 1, wn = wid >> 1;        // warp tile 64m x 32n
    const int jbase = blockIdx.x * 128;
    const int rbase = blockIdx.y * 128;
    const uint32_t smb = smem_u32(sm);

    const int sel = lane >> 3, rin = lane & 7;

    uint32_t baseA[4]; int vA[4];
#pragma unroll
    for (int i = 0; i < 4; ++i) {
        int row = wm * 64 + i * 16 + rin + ((sel & 1) << 3);
        baseA[i] = (uint32_t)(row * 128);
        vA[i] = row & 7;
    }
    const int hA = sel >> 1;
    uint32_t baseB[2]; int vB[2];
#pragma unroll
    for (int p = 0; p < 2; ++p) {
        int row = wn * 32 + p * 16 + rin + ((sel >> 1) << 3);
        baseB[p] = (uint32_t)(16384 + row * 128);
        vB[p] = row & 7;
    }
    const int hB = sel & 1;

    // cp.async: 8 x 16B per thread per stage (A: e 0..3, B: e 4..7)
    const __half* sp[8];
    uint32_t doff[8];
#pragma unroll
    for (int e = 0; e < 8; ++e) {
        int idx = tid + (e & 3) * 256;             // 0..1023
        int row = idx >> 3, c = idx & 7;
        if (e < 4) {
            sp[e] = g_ahf + (size_t)(rbase + row) * DDIM + c * 8;
            doff[e] = (uint32_t)(row * 128 + ((c ^ (row & 7)) << 4));
        } else {
            sp[e] = g_whf + (size_t)(jbase + row) * DDIM + c * 8;
            doff[e] = (uint32_t)(16384 + row * 128 + ((c ^ (row & 7)) << 4));
        }
    }

    uint32_t acc[4][4][2];
#pragma unroll
    for (int i = 0; i < 4; ++i)
#pragma unroll
        for (int j = 0; j < 4; ++j) { acc[i][j][0] = 0u; acc[i][j][1] = 0u; }

#define LOAD_STAGE(st, ko)                                                \
    do {                                                                  \
        uint32_t sb_ = smb + (st) * STAGE_B;                              \
        _Pragma("unroll")                                                 \
        for (int e = 0; e < 8; ++e) cp16(sb_ + doff[e], sp[e] + (ko));    \
        asm volatile("cp.async.commit_group;" ::: "memory");              \
    } while (0)

    LOAD_STAGE(0, 0);
    LOAD_STAGE(1, 64);

#pragma unroll
    for (int c = 0; c < 4; ++c) {
        if (c < 3) asm volatile("cp.async.wait_group 1;" ::: "memory");
        else       asm volatile("cp.async.wait_group 0;" ::: "memory");
        __syncthreads();
        if (c < 2) LOAD_STAGE(c + 2 - ((c + 2 >= 3) ? 3 : 0), (c + 2) * 64);
        uint32_t sb = smb + (c % 3) * STAGE_B;
#pragma unroll
        for (int ks = 0; ks < 4; ++ks) {          // 4 x K16 per chunk
            uint32_t a[4][4], bf[4][2];
#pragma unroll
            for (int i = 0; i < 4; ++i)
                ldm4(a[i], sb + baseA[i] + (((ks * 2 + hA) ^ vA[i]) << 4));
#pragma unroll
            for (int p = 0; p < 2; ++p) {
                uint32_t r4[4];
                ldm4(r4, sb + baseB[p] + (((ks * 2 + hB) ^ vB[p]) << 4));
                bf[2 * p][0] = r4[0]; bf[2 * p][1] = r4[1];
                bf[2 * p + 1][0] = r4[2]; bf[2 * p + 1][1] = r4[3];
            }
#pragma unroll
            for (int i = 0; i < 4; ++i)
#pragma unroll
                for (int j = 0; j < 4; ++j)
                    mma16816h(acc[i][j], a[i], bf[j]);
        }
    }
#undef LOAD_STAGE

    // epilogue: unpack fp16 acc; scores = acc - 0.5*wsq; store bf16; argmax
    const int lq = lane >> 2, lr = lane & 3;
    float bv[8]; int bj[8];
#pragma unroll
    for (int s = 0; s < 8; ++s) { bv[s] = -3.4e38f; bj[s] = 0; }

#pragma unroll
    for (int j = 0; j < 4; ++j) {
        int col = jbase + wn * 32 + j * 8 + lr * 2;
        float2 wq = *reinterpret_cast<const float2*>(&g_wsq[col]);
#pragma unroll
        for (int i = 0; i < 4; ++i) {
#pragma unroll
            for (int h = 0; h < 2; ++h) {
                float2 f = __half22float2(*reinterpret_cast<__half2*>(&acc[i][j][h]));
                float s0 = f.x - 0.5f * wq.x;
                float s1 = f.y - 0.5f * wq.y;
                int grow = rbase + wm * 64 + i * 16 + lq + h * 8;
                __nv_bfloat162 pr = __floats2bfloat162_rn(s0, s1);
                st_cs32(&g_scores[(size_t)grow * VCODES + col],
                        *reinterpret_cast<uint32_t*>(&pr));
                int slot = i * 2 + h;
                if (s0 > bv[slot]) { bv[slot] = s0; bj[slot] = col; }
                if (s1 > bv[slot]) { bv[slot] = s1; bj[slot] = col + 1; }
            }
        }
    }
#pragma unroll
    for (int s = 0; s < 8; ++s) {
        unsigned long long key = ((unsigned long long)enc_f(bv[s]) << 32) |
                                 (unsigned)(0xFFFFFFFFu - (unsigned)bj[s]);
#pragma unroll
        for (int o = 1; o < 4; o <<= 1) {
            unsigned long long v = __shfl_xor_sync(0xFFFFFFFFu, key, o);
            if (v > key) key = v;
        }
        if (lr == 0) {
            int grow = rbase + wm * 64 + (s >> 1) * 16 + lq + (s & 1) * 8;
            atomicMax(&g_best[grow], key);
            atomicMax(&g_tilemax[grow * NTILES + blockIdx.x], (unsigned)(key >> 32));
        }
    }
}

// ---------------------------------------------------------------------------
// Repair: tile-max-guided. Per-row warp reads 64 tile maxima, scans only
// flagged tiles' scores, exact fp32 recompute of candidates within MARGIN.
__global__ void k_repair(const float* __restrict__ x, const float* __restrict__ w,
                         float* __restrict__ out) {
    int r = blockIdx.x * 8 + (threadIdx.x >> 5);
    int lane = threadIdx.x & 31;
    unsigned long long kk = g_best[r];
    float thr = dec_f((unsigned)(kk >> 32)) - MARGIN;
    int b = r >> 12, s = r & 4095;
    const float* xb = x + (size_t)b * 1048576 + s;
    float bestv = -3.4e38f;
    int   bestj = 0;
    const __nv_bfloat16* srow = g_scores + (size_t)r * VCODES;
#pragma unroll
    for (int half = 0; half < 2; ++half) {
        unsigned tm = g_tilemax[r * NTILES + half * 32 + lane];
        unsigned act = __ballot_sync(0xFFFFFFFFu, dec_f(tm) >= thr);
        while (act) {
            int t = __ffs(act) - 1; act &= act - 1;
            int tile = half * 32 + t;
            // scan this tile's 128 scores: 4 per lane (uint2 = 4 bf16)
            uint2 v = *reinterpret_cast<const uint2*>(srow + tile * 128 + lane * 4);
            unsigned m = 0;
            unsigned wds[2] = {v.x, v.y};
#pragma unroll
            for (int q = 0; q < 2; ++q) {
                __nv_bfloat162 h2 = *reinterpret_cast<__nv_bfloat162*>(&wds[q]);
                float2 f = __bfloat1622float2(h2);
                if (f.x >= thr) m |= 1u << (2 * q);
                if (f.y >= thr) m |= 1u << (2 * q + 1);
            }
            unsigned act2 = __ballot_sync(0xFFFFFFFFu, m != 0);
            while (act2) {
                int src = __ffs(act2) - 1; act2 &= act2 - 1;
                unsigned mm = __shfl_sync(0xFFFFFFFFu, m, src);
                while (mm) {
                    int bit = __ffs(mm) - 1; mm &= mm - 1;
                    int j = tile * 128 + src * 4 + bit;
                    const float* wr = w + (size_t)j * DDIM;
                    float p = 0.0f;
#pragma unroll
                    for (int q = 0; q < 8; ++q) {
                        int k = lane + q * 32;
                        p += xb[(size_t)k * SPAT] * wr[k];
                    }
#pragma unroll
                    for (int o = 16; o; o >>= 1) p += __shfl_xor_sync(0xFFFFFFFFu, p, o);
                    float sc = p - 0.5f * g_wsq[j];
                    if (sc > bestv) { bestv = sc; bestj = j; }   // ascending j tie-break
                }
            }
        }
    }
    if (lane == 0) {
        g_idx[r] = bestj;
        out[O_IDX + r] = (float)bestj;
        atomicAdd(&g_counts[bestj], 1.0f);
    }
}

// ---------------------------------------------------------------------------
// quant write (coalesced over spatial), enc_sum atomics, quant_diff.
// 8x d-split for parallelism: grid 2048 = 256 spatial-chunks x 8 d-groups.
__global__ void k_assign(const float* __restrict__ x, const float* __restrict__ w,
                         float* __restrict__ out) {
    __shared__ int sidx[128];
    __shared__ float red[8];
    int bi = blockIdx.x;
    int sc = bi & 255, dgp = bi >> 8;             // spatial chunk, d-group
    int b = sc >> 5, s0 = (sc & 31) * 128;
    int tid = threadIdx.x, ts = tid & 127, dh = tid >> 7;
    if (tid < 128) sidx[tid] = g_idx[b * SPAT + s0 + tid];
    __syncthreads();
    int j = sidx[ts];
    const float* wr = w + (size_t)j * DDIM;
    float* er = g_encsum + (size_t)j * DDIM;
    size_t basex = (size_t)b * 1048576 + s0 + ts;
    int d0 = dgp * 32;
    float qd = 0.0f;
#pragma unroll
    for (int k = 0; k < 16; ++k) {
        int d = d0 + dh + k * 2;
        size_t off = basex + (size_t)d * SPAT;
        float xv = x[off];
        float wv = __ldg(wr + d);
        out[O_QUANT + off] = (wv - xv) + xv;
        float df = xv - wv;
        qd += df * df;
        atomicAdd(er + d, xv);
    }
#pragma unroll
    for (int o = 16; o; o >>= 1) qd += __shfl_xor_sync(0xFFFFFFFFu, qd, o);
    if ((tid & 31) == 0) red[tid >> 5] = qd;
    __syncthreads();
    if (tid == 0) {
        float t = 0.0f;
#pragma unroll
        for (int i = 0; i < 8; ++i) t += red[i];
        atomicAdd(&g_qd, t);
    }
}

// ---------------------------------------------------------------------------
__global__ void k_update(const float* __restrict__ N, const float* __restrict__ z_avg,
                         float* __restrict__ out) {
    int i = blockIdx.x * 256 + threadIdx.x;
    if (i >= VCODES * DDIM) return;
    int v = i >> 8, d = i & 255;
    float gamma = 0.99f, om = 0.01f, eps = 1e-7f;
    float n  = gamma * g_sumN + om * (float)MROWS;
    float nN = gamma * N[v] + om * g_counts[v];
    float wgt = (nN + eps) / (n + (float)VCODES * eps) * n;
    float za = gamma * z_avg[i] + om * g_encsum[i];
    out[O_ZAVG + i] = za;
    out[O_NEWW + i] = za / wgt;
    if (d == 0) out[O_NEWN + v] = nN;
    if (i == 0) out[O_QD] = g_qd * (1.0f / 8388608.0f);
}

// ---------------------------------------------------------------------------
extern "C" void kernel_launch(void* const* d_in, const int* in_sizes, int n_in,
                              void* d_out, int out_size) {
    const float* x    = (const float*)d_in[0];
    const float* w    = (const float*)d_in[1];
    const float* N    = (const float*)d_in[2];
    const float* zavg = (const float*)d_in[3];
    float* out = (float*)d_out;

    cudaFuncSetAttribute(k_gemm, cudaFuncAttributeMaxDynamicSharedMemorySize, SMEM_DYN);

    k_zero<<<8192, 256>>>();
    k_prep_x<<<dim3(8, 128, 8), dim3(32, 8)>>>(x);
    k_prep_w<<<1024, 256>>>(w, N);
    k_gemm<<<dim3(VCODES / 128, MROWS / 128), 256, SMEM_DYN>>>();
    k_repair<<<MROWS / 8, 256>>>(x, w, out);
    k_assign<<<2048, 256>>>(x, w, out);
    k_update<<<VCODES * DDIM / 256, 256>>>(N, zavg, out);
}

// round 14
// speedup vs baseline: 1.2608x; 1.0981x over previous
#include <cuda_runtime.h>
#include <cuda_bf16.h>
#include <cuda_fp16.h>
#include <cstdint>

// Problem constants
#define VCODES 8192
#define DDIM   256
#define MROWS  32768      // 8 * 16*16*16
#define SPAT   4096       // 16*16*16
#define NTILES 64         // VCODES / 128

// Output layout (concatenated f32)
#define O_QUANT 0ul
#define O_IDX   8388608ul
#define O_QD    8421376ul
#define O_NEWN  8421377ul
#define O_ZAVG  8429569ul
#define O_NEWW  10526721ul

#define MARGIN 3.0f

// ---------------------------------------------------------------------------
// Scratch (device globals; no allocations allowed)
__device__ int   g_idx[MROWS];
__device__ float g_counts[VCODES];
__device__ float g_encsum[VCODES * DDIM];
__device__ float g_wsq[VCODES];
__device__ float g_sumN;
__device__ float g_qd;
__device__ unsigned g_tilemax[MROWS * NTILES];   // monotone-encoded fp32 per (row, tile)
__device__ __half g_ahf[MROWS * DDIM];           // flat x, fp16
__device__ __half g_whf[VCODES * DDIM];          // weight, fp16
__device__ __nv_bfloat16 g_scores[(size_t)MROWS * VCODES];  // coarse scores

// ---------------------------------------------------------------------------
__device__ __forceinline__ uint32_t smem_u32(const void* p) {
    uint32_t a;
    asm("{ .reg .u64 t; cvta.to.shared.u64 t, %1; cvt.u32.u64 %0, t; }" : "=r"(a) : "l"(p));
    return a;
}
__device__ __forceinline__ void cp16(uint32_t dst, const void* src) {
    asm volatile("cp.async.cg.shared.global [%0], [%1], 16;" :: "r"(dst), "l"(src) : "memory");
}
__device__ __forceinline__ void ldm4(uint32_t* r, uint32_t addr) {
    asm volatile("ldmatrix.sync.aligned.m8n8.x4.shared.b16 {%0,%1,%2,%3}, [%4];"
                 : "=r"(r[0]), "=r"(r[1]), "=r"(r[2]), "=r"(r[3]) : "r"(addr));
}
// fp16-accumulate HMMA
__device__ __forceinline__ void mma16816h(uint32_t* c, const uint32_t* a, const uint32_t* b) {
    asm volatile(
        "mma.sync.aligned.m16n8k16.row.col.f16.f16.f16.f16 "
        "{%0,%1}, {%2,%3,%4,%5}, {%6,%7}, {%0,%1};"
        : "+r"(c[0]), "+r"(c[1])
        : "r"(a[0]), "r"(a[1]), "r"(a[2]), "r"(a[3]), "r"(b[0]), "r"(b[1]));
}
__device__ __forceinline__ void st_cs32(void* p, uint32_t v) {
    asm volatile("st.global.cs.b32 [%0], %1;" :: "l"(p), "r"(v) : "memory");
}
__device__ __forceinline__ unsigned enc_f(float f) {
    unsigned u = __float_as_uint(f);
    return (u & 0x80000000u) ? ~u : (u | 0x80000000u);
}
__device__ __forceinline__ float dec_f(unsigned u) {
    unsigned b = (u & 0x80000000u) ? (u & 0x7FFFFFFFu) : ~u;
    return __uint_as_float(b);
}

// ---------------------------------------------------------------------------
// Fused prep: role by block range.
//   q in [0, 8192)      : zero encsum/counts/qd
//   q in [8192, 9216)   : weight -> fp16, wsq
//   q in [9216, 17408)  : x transpose -> fp16 rows
__global__ void k_prep(const float* __restrict__ x, const float* __restrict__ w) {
    __shared__ float t[32][33];
    int q = blockIdx.x;
    int tid = threadIdx.x;
    if (q < 8192) {
        int i = q * 256 + tid;
        g_encsum[i] = 0.0f;                       // covers 2097152 exactly
        if (i < VCODES) g_counts[i] = 0.0f;
        if (i == 0) g_qd = 0.0f;
        return;
    }
    if (q < 9216) {
        int gid = (q - 8192) * 256 + tid;
        int v = gid >> 5, lane = gid & 31;
        const float* row = w + (size_t)v * DDIM;
        float s = 0.0f;
#pragma unroll
        for (int k = lane; k < DDIM; k += 32) {
            float a = row[k];
            s += a * a;
            g_whf[(size_t)v * DDIM + k] = __float2half_rn(a);
        }
#pragma unroll
        for (int o = 16; o; o >>= 1) s += __shfl_xor_sync(0xFFFFFFFFu, s, o);
        if (lane == 0) g_wsq[v] = s;
        return;
    }
    int qp = q - 9216;
    int k0 = (qp & 7) * 32, s0 = ((qp >> 3) & 127) * 32, b = qp >> 10;
    int tx = tid & 31, ty = tid >> 5;             // (32, 8)
#pragma unroll
    for (int i = 0; i < 4; ++i)
        t[ty + i * 8][tx] = x[(size_t)b * 1048576 + (size_t)(k0 + ty + i * 8) * SPAT + s0 + tx];
    __syncthreads();
#pragma unroll
    for (int i = 0; i < 4; ++i) {
        int r = b * SPAT + s0 + ty + i * 8;
        g_ahf[(size_t)r * DDIM + k0 + tx] = __float2half_rn(t[tx][ty + i * 8]);
    }
}

// ---------------------------------------------------------------------------
// fp16-accum HMMA GEMM: CTA 128x128, 8 warps of 64x32, K-chunk=64, 3-stage
// x 32KB pipeline, 96KB dyn smem. Epilogue: plain-store per-row tile max.
#define STAGE_B 32768
#define SMEM_DYN (3 * STAGE_B)

__global__ __launch_bounds__(256, 2) void k_gemm() {
    extern __shared__ __align__(16) char sm[];
    const int tid = threadIdx.x;
    const int lane = tid & 31, wid = tid >> 5;
    const int wm = wid & 1, wn = wid >> 1;        // warp tile 64m x 32n
    const int jbase = blockIdx.x * 128;
    const int rbase = blockIdx.y * 128;
    const uint32_t smb = smem_u32(sm);

    const int sel = lane >> 3, rin = lane & 7;

    uint32_t baseA[4]; int vA[4];
#pragma unroll
    for (int i = 0; i < 4; ++i) {
        int row = wm * 64 + i * 16 + rin + ((sel & 1) << 3);
        baseA[i] = (uint32_t)(row * 128);
        vA[i] = row & 7;
    }
    const int hA = sel >> 1;
    uint32_t baseB[2]; int vB[2];
#pragma unroll
    for (int p = 0; p < 2; ++p) {
        int row = wn * 32 + p * 16 + rin + ((sel >> 1) << 3);
        baseB[p] = (uint32_t)(16384 + row * 128);
        vB[p] = row & 7;
    }
    const int hB = sel & 1;

    const __half* sp[8];
    uint32_t doff[8];
#pragma unroll
    for (int e = 0; e < 8; ++e) {
        int idx = tid + (e & 3) * 256;             // 0..1023
        int row = idx >> 3, c = idx & 7;
        if (e < 4) {
            sp[e] = g_ahf + (size_t)(rbase + row) * DDIM + c * 8;
            doff[e] = (uint32_t)(row * 128 + ((c ^ (row & 7)) << 4));
        } else {
            sp[e] = g_whf + (size_t)(jbase + row) * DDIM + c * 8;
            doff[e] = (uint32_t)(16384 + row * 128 + ((c ^ (row & 7)) << 4));
        }
    }

    uint32_t acc[4][4][2];
#pragma unroll
    for (int i = 0; i < 4; ++i)
#pragma unroll
        for (int j = 0; j < 4; ++j) { acc[i][j][0] = 0u; acc[i][j][1] = 0u; }

#define LOAD_STAGE(st, ko)                                                \
    do {                                                                  \
        uint32_t sb_ = smb + (st) * STAGE_B;                              \
        _Pragma("unroll")                                                 \
        for (int e = 0; e < 8; ++e) cp16(sb_ + doff[e], sp[e] + (ko));    \
        asm volatile("cp.async.commit_group;" ::: "memory");              \
    } while (0)

    LOAD_STAGE(0, 0);
    LOAD_STAGE(1, 64);

#pragma unroll
    for (int c = 0; c < 4; ++c) {
        if (c < 3) asm volatile("cp.async.wait_group 1;" ::: "memory");
        else       asm volatile("cp.async.wait_group 0;" ::: "memory");
        __syncthreads();
        if (c < 2) LOAD_STAGE(c + 2 - ((c + 2 >= 3) ? 3 : 0), (c + 2) * 64);
        uint32_t sb = smb + (c % 3) * STAGE_B;
#pragma unroll
        for (int ks = 0; ks < 4; ++ks) {
            uint32_t a[4][4], bf[4][2];
#pragma unroll
            for (int i = 0; i < 4; ++i)
                ldm4(a[i], sb + baseA[i] + (((ks * 2 + hA) ^ vA[i]) << 4));
#pragma unroll
            for (int p = 0; p < 2; ++p) {
                uint32_t r4[4];
                ldm4(r4, sb + baseB[p] + (((ks * 2 + hB) ^ vB[p]) << 4));
                bf[2 * p][0] = r4[0]; bf[2 * p][1] = r4[1];
                bf[2 * p + 1][0] = r4[2]; bf[2 * p + 1][1] = r4[3];
            }
#pragma unroll
            for (int i = 0; i < 4; ++i)
#pragma unroll
                for (int j = 0; j < 4; ++j)
                    mma16816h(acc[i][j], a[i], bf[j]);
        }
    }
#undef LOAD_STAGE

    // epilogue: scores = acc - 0.5*wsq; store bf16; per-row tile max (no atomics)
    const int lq = lane >> 2, lr = lane & 3;
    float bv[8];
#pragma unroll
    for (int s = 0; s < 8; ++s) bv[s] = -3.4e38f;

#pragma unroll
    for (int j = 0; j < 4; ++j) {
        int col = jbase + wn * 32 + j * 8 + lr * 2;
        float2 wq = *reinterpret_cast<const float2*>(&g_wsq[col]);
#pragma unroll
        for (int i = 0; i < 4; ++i) {
#pragma unroll
            for (int h = 0; h < 2; ++h) {
                float2 f = __half22float2(*reinterpret_cast<__half2*>(&acc[i][j][h]));
                float s0 = f.x - 0.5f * wq.x;
                float s1 = f.y - 0.5f * wq.y;
                int grow = rbase + wm * 64 + i * 16 + lq + h * 8;
                __nv_bfloat162 pr = __floats2bfloat162_rn(s0, s1);
                st_cs32(&g_scores[(size_t)grow * VCODES + col],
                        *reinterpret_cast<uint32_t*>(&pr));
                int slot = i * 2 + h;
                bv[slot] = fmaxf(bv[slot], fmaxf(s0, s1));
            }
        }
    }
#pragma unroll
    for (int s = 0; s < 8; ++s) {
#pragma unroll
        for (int o = 1; o < 4; o <<= 1)
            bv[s] = fmaxf(bv[s], __shfl_xor_sync(0xFFFFFFFFu, bv[s], o));
    }
    __syncthreads();                              // done with stage smem
    float* red = (float*)sm;                      // 128 x 4 floats
    if (lr == 0) {
#pragma unroll
        for (int s = 0; s < 8; ++s) {
            int rl = wm * 64 + (s >> 1) * 16 + lq + (s & 1) * 8;
            red[rl * 4 + wn] = bv[s];
        }
    }
    __syncthreads();
    if (tid < 128) {
        float m = fmaxf(fmaxf(red[tid * 4], red[tid * 4 + 1]),
                        fmaxf(red[tid * 4 + 2], red[tid * 4 + 3]));
        g_tilemax[(rbase + tid) * NTILES + blockIdx.x] = enc_f(m);
    }
}

// ---------------------------------------------------------------------------
// Repair: thr from tile maxima; scan flagged tiles' scores; exact fp32
// recompute of candidates. Ascending-j order preserves first-index tie-break.
__global__ void k_repair(const float* __restrict__ x, const float* __restrict__ w,
                         float* __restrict__ out) {
    int r = blockIdx.x * 8 + (threadIdx.x >> 5);
    int lane = threadIdx.x & 31;
    const unsigned* tmrow = g_tilemax + r * NTILES;
    unsigned t0 = tmrow[lane], t1 = tmrow[lane + 32];
    unsigned tmx = max(t0, t1);                   // monotone encoding: u32 max ok
#pragma unroll
    for (int o = 16; o; o >>= 1) tmx = max(tmx, __shfl_xor_sync(0xFFFFFFFFu, tmx, o));
    float thr = dec_f(tmx) - MARGIN;
    int b = r >> 12, s = r & 4095;
    const float* xb = x + (size_t)b * 1048576 + s;
    float bestv = -3.4e38f;
    int   bestj = 0;
    const __nv_bfloat16* srow = g_scores + (size_t)r * VCODES;
#pragma unroll
    for (int half = 0; half < 2; ++half) {
        unsigned tm = half ? t1 : t0;
        unsigned act = __ballot_sync(0xFFFFFFFFu, dec_f(tm) >= thr);
        while (act) {
            int t = __ffs(act) - 1; act &= act - 1;
            int tile = half * 32 + t;
            uint2 v = *reinterpret_cast<const uint2*>(srow + tile * 128 + lane * 4);
            unsigned m = 0;
            unsigned wds[2] = {v.x, v.y};
#pragma unroll
            for (int q = 0; q < 2; ++q) {
                __nv_bfloat162 h2 = *reinterpret_cast<__nv_bfloat162*>(&wds[q]);
                float2 f = __bfloat1622float2(h2);
                if (f.x >= thr) m |= 1u << (2 * q);
                if (f.y >= thr) m |= 1u << (2 * q + 1);
            }
            unsigned act2 = __ballot_sync(0xFFFFFFFFu, m != 0);
            while (act2) {
                int src = __ffs(act2) - 1; act2 &= act2 - 1;
                unsigned mm = __shfl_sync(0xFFFFFFFFu, m, src);
                while (mm) {
                    int bit = __ffs(mm) - 1; mm &= mm - 1;
                    int j = tile * 128 + src * 4 + bit;
                    const float* wr = w + (size_t)j * DDIM;
                    float p = 0.0f;
#pragma unroll
                    for (int q = 0; q < 8; ++q) {
                        int k = lane + q * 32;
                        p += xb[(size_t)k * SPAT] * wr[k];
                    }
#pragma unroll
                    for (int o = 16; o; o >>= 1) p += __shfl_xor_sync(0xFFFFFFFFu, p, o);
                    float sc = p - 0.5f * g_wsq[j];
                    if (sc > bestv) { bestv = sc; bestj = j; }
                }
            }
        }
    }
    if (lane == 0) {
        g_idx[r] = bestj;
        out[O_IDX + r] = (float)bestj;
        atomicAdd(&g_counts[bestj], 1.0f);
    }
}

// ---------------------------------------------------------------------------
// quant write + enc_sum atomics + quant_diff (8x d-split). Block 2048
// computes sum(N) with a plain smem reduction (no atomic, no pre-zero).
__global__ void k_assign(const float* __restrict__ x, const float* __restrict__ w,
                         const float* __restrict__ N, float* __restrict__ out) {
    __shared__ int sidx[128];
    __shared__ float red[8];
    int bi = blockIdx.x;
    int tid = threadIdx.x;
    if (bi == 2048) {                             // sum(N) side job
        float s = 0.0f;
        for (int i = tid; i < VCODES; i += 256) s += N[i];
#pragma unroll
        for (int o = 16; o; o >>= 1) s += __shfl_xor_sync(0xFFFFFFFFu, s, o);
        if ((tid & 31) == 0) red[tid >> 5] = s;
        __syncthreads();
        if (tid == 0) {
            float t = 0.0f;
#pragma unroll
            for (int i = 0; i < 8; ++i) t += red[i];
            g_sumN = t;
        }
        return;
    }
    int sc = bi & 255, dgp = bi >> 8;             // spatial chunk, d-group
    int b = sc >> 5, s0 = (sc & 31) * 128;
    int ts = tid & 127, dh = tid >> 7;
    if (tid < 128) sidx[tid] = g_idx[b * SPAT + s0 + tid];
    __syncthreads();
    int j = sidx[ts];
    const float* wr = w + (size_t)j * DDIM;
    float* er = g_encsum + (size_t)j * DDIM;
    size_t basex = (size_t)b * 1048576 + s0 + ts;
    int d0 = dgp * 32;
    float qd = 0.0f;
#pragma unroll
    for (int k = 0; k < 16; ++k) {
        int d = d0 + dh + k * 2;
        size_t off = basex + (size_t)d * SPAT;
        float xv = x[off];
        float wv = __ldg(wr + d);
        out[O_QUANT + off] = (wv - xv) + xv;
        float df = xv - wv;
        qd += df * df;
        atomicAdd(er + d, xv);
    }
#pragma unroll
    for (int o = 16; o; o >>= 1) qd += __shfl_xor_sync(0xFFFFFFFFu, qd, o);
    if ((tid & 31) == 0) red[tid >> 5] = qd;
    __syncthreads();
    if (tid == 0) {
        float t = 0.0f;
#pragma unroll
        for (int i = 0; i < 8; ++i) t += red[i];
        atomicAdd(&g_qd, t);
    }
}

// ---------------------------------------------------------------------------
__global__ void k_update(const float* __restrict__ N, const float* __restrict__ z_avg,
                         float* __restrict__ out) {
    int i = blockIdx.x * 256 + threadIdx.x;
    if (i >= VCODES * DDIM) return;
    int v = i >> 8, d = i & 255;
    float gamma = 0.99f, om = 0.01f, eps = 1e-7f;
    float n  = gamma * g_sumN + om * (float)MROWS;
    float nN = gamma * N[v] + om * g_counts[v];
    float wgt = (nN + eps) / (n + (float)VCODES * eps) * n;
    float za = gamma * z_avg[i] + om * g_encsum[i];
    out[O_ZAVG + i] = za;
    out[O_NEWW + i] = za / wgt;
    if (d == 0) out[O_NEWN + v] = nN;
    if (i == 0) out[O_QD] = g_qd * (1.0f / 8388608.0f);
}

// ---------------------------------------------------------------------------
extern "C" void kernel_launch(void* const* d_in, const int* in_sizes, int n_in,
                              void* d_out, int out_size) {
    const float* x    = (const float*)d_in[0];
    const float* w    = (const float*)d_in[1];
    const float* N    = (const float*)d_in[2];
    const float* zavg = (const float*)d_in[3];
    float* out = (float*)d_out;

    cudaFuncSetAttribute(k_gemm, cudaFuncAttributeMaxDynamicSharedMemorySize, SMEM_DYN);

    k_prep<<<17408, 256>>>(x, w);
    k_gemm<<<dim3(VCODES / 128, MROWS / 128), 256, SMEM_DYN>>>();
    k_repair<<<MROWS / 8, 256>>>(x, w, out);
    k_assign<<<2049, 256>>>(x, w, N, out);
    k_update<<<VCODES * DDIM / 256, 256>>>(N, zavg, out);
}

// round 15
// speedup vs baseline: 1.4858x; 1.1785x over previous
#include <cuda_runtime.h>
#include <cuda_bf16.h>
#include <cuda_fp16.h>
#include <cstdint>

// Problem constants
#define VCODES 8192
#define DDIM   256
#define MROWS  32768      // 8 * 16*16*16
#define SPAT   4096       // 16*16*16
#define NTILES 64         // VCODES / 128

// Output layout (concatenated f32)
#define O_QUANT 0ul
#define O_IDX   8388608ul
#define O_QD    8421376ul
#define O_NEWN  8421377ul
#define O_ZAVG  8429569ul
#define O_NEWW  10526721ul

#define MARGIN 3.0f

// ---------------------------------------------------------------------------
// Scratch (device globals; no allocations allowed)
__device__ int   g_idx[MROWS];
__device__ float g_counts[VCODES];
__device__ float g_encsum[VCODES * DDIM];
__device__ float g_wsq[VCODES];
__device__ float g_sumN;
__device__ float g_qd;
__device__ unsigned g_tilemax[MROWS * NTILES];   // monotone-encoded fp32 per (row, tile)
__device__ __half g_ahf[MROWS * DDIM];           // flat x, fp16
__device__ __half g_whf[VCODES * DDIM];          // weight, fp16
__device__ __nv_bfloat16 g_scores[(size_t)MROWS * VCODES];  // coarse scores

// ---------------------------------------------------------------------------
__device__ __forceinline__ uint32_t smem_u32(const void* p) {
    uint32_t a;
    asm("{ .reg .u64 t; cvta.to.shared.u64 t, %1; cvt.u32.u64 %0, t; }" : "=r"(a) : "l"(p));
    return a;
}
__device__ __forceinline__ void cp16(uint32_t dst, const void* src) {
    asm volatile("cp.async.cg.shared.global [%0], [%1], 16;" :: "r"(dst), "l"(src) : "memory");
}
__device__ __forceinline__ void ldm4(uint32_t* r, uint32_t addr) {
    asm volatile("ldmatrix.sync.aligned.m8n8.x4.shared.b16 {%0,%1,%2,%3}, [%4];"
                 : "=r"(r[0]), "=r"(r[1]), "=r"(r[2]), "=r"(r[3]) : "r"(addr));
}
// fp16-accumulate HMMA
__device__ __forceinline__ void mma16816h(uint32_t* c, const uint32_t* a, const uint32_t* b) {
    asm volatile(
        "mma.sync.aligned.m16n8k16.row.col.f16.f16.f16.f16 "
        "{%0,%1}, {%2,%3,%4,%5}, {%6,%7}, {%0,%1};"
        : "+r"(c[0]), "+r"(c[1])
        : "r"(a[0]), "r"(a[1]), "r"(a[2]), "r"(a[3]), "r"(b[0]), "r"(b[1]));
}
__device__ __forceinline__ void st_cs32(void* p, uint32_t v) {
    asm volatile("st.global.cs.b32 [%0], %1;" :: "l"(p), "r"(v) : "memory");
}
// vector fp32 reduction (sm_90+): one instruction adds 4 consecutive floats
__device__ __forceinline__ void red4(float* p, float a, float b, float c, float d) {
    asm volatile("red.global.add.v4.f32 [%0], {%1, %2, %3, %4};"
                 :: "l"(p), "f"(a), "f"(b), "f"(c), "f"(d) : "memory");
}
__device__ __forceinline__ unsigned enc_f(float f) {
    unsigned u = __float_as_uint(f);
    return (u & 0x80000000u) ? ~u : (u | 0x80000000u);
}
__device__ __forceinline__ float dec_f(unsigned u) {
    unsigned b = (u & 0x80000000u) ? (u & 0x7FFFFFFFu) : ~u;
    return __uint_as_float(b);
}

// ---------------------------------------------------------------------------
// Fused prep: role by block range.
//   q in [0, 8192)      : zero encsum/counts/qd
//   q in [8192, 9216)   : weight -> fp16, wsq
//   q in [9216, 17408)  : x transpose -> fp16 rows
//   q == 17408          : sum(N)
__global__ void k_prep(const float* __restrict__ x, const float* __restrict__ w,
                       const float* __restrict__ N) {
    __shared__ float t[32][33];
    __shared__ float red[8];
    int q = blockIdx.x;
    int tid = threadIdx.x;
    if (q < 8192) {
        int i = q * 256 + tid;
        g_encsum[i] = 0.0f;                       // covers 2097152 exactly
        if (i < VCODES) g_counts[i] = 0.0f;
        if (i == 0) g_qd = 0.0f;
        return;
    }
    if (q < 9216) {
        int gid = (q - 8192) * 256 + tid;
        int v = gid >> 5, lane = gid & 31;
        const float* row = w + (size_t)v * DDIM;
        float s = 0.0f;
#pragma unroll
        for (int k = lane; k < DDIM; k += 32) {
            float a = row[k];
            s += a * a;
            g_whf[(size_t)v * DDIM + k] = __float2half_rn(a);
        }
#pragma unroll
        for (int o = 16; o; o >>= 1) s += __shfl_xor_sync(0xFFFFFFFFu, s, o);
        if (lane == 0) g_wsq[v] = s;
        return;
    }
    if (q == 17408) {                             // sum(N)
        float s = 0.0f;
        for (int i = tid; i < VCODES; i += 256) s += N[i];
#pragma unroll
        for (int o = 16; o; o >>= 1) s += __shfl_xor_sync(0xFFFFFFFFu, s, o);
        if ((tid & 31) == 0) red[tid >> 5] = s;
        __syncthreads();
        if (tid == 0) {
            float tt = 0.0f;
#pragma unroll
            for (int i = 0; i < 8; ++i) tt += red[i];
            g_sumN = tt;
        }
        return;
    }
    int qp = q - 9216;
    int k0 = (qp & 7) * 32, s0 = ((qp >> 3) & 127) * 32, b = qp >> 10;
    int tx = tid & 31, ty = tid >> 5;             // (32, 8)
#pragma unroll
    for (int i = 0; i < 4; ++i)
        t[ty + i * 8][tx] = x[(size_t)b * 1048576 + (size_t)(k0 + ty + i * 8) * SPAT + s0 + tx];
    __syncthreads();
#pragma unroll
    for (int i = 0; i < 4; ++i) {
        int r = b * SPAT + s0 + ty + i * 8;
        g_ahf[(size_t)r * DDIM + k0 + tx] = __float2half_rn(t[tx][ty + i * 8]);
    }
}

// ---------------------------------------------------------------------------
// fp16-accum HMMA GEMM: CTA 128x128, 8 warps of 64x32, K-chunk=64, 3-stage
// x 32KB pipeline, 96KB dyn smem. Epilogue: plain-store per-row tile max.
#define STAGE_B 32768
#define SMEM_DYN (3 * STAGE_B)

__global__ __launch_bounds__(256, 2) void k_gemm() {
    extern __shared__ __align__(16) char sm[];
    const int tid = threadIdx.x;
    const int lane = tid & 31, wid = tid >> 5;
    const int wm = wid & 1, wn = wid >> 1;        // warp tile 64m x 32n
    const int jbase = blockIdx.x * 128;
    const int rbase = blockIdx.y * 128;
    const uint32_t smb = smem_u32(sm);

    const int sel = lane >> 3, rin = lane & 7;

    uint32_t baseA[4]; int vA[4];
#pragma unroll
    for (int i = 0; i < 4; ++i) {
        int row = wm * 64 + i * 16 + rin + ((sel & 1) << 3);
        baseA[i] = (uint32_t)(row * 128);
        vA[i] = row & 7;
    }
    const int hA = sel >> 1;
    uint32_t baseB[2]; int vB[2];
#pragma unroll
    for (int p = 0; p < 2; ++p) {
        int row = wn * 32 + p * 16 + rin + ((sel >> 1) << 3);
        baseB[p] = (uint32_t)(16384 + row * 128);
        vB[p] = row & 7;
    }
    const int hB = sel & 1;

    const __half* sp[8];
    uint32_t doff[8];
#pragma unroll
    for (int e = 0; e < 8; ++e) {
        int idx = tid + (e & 3) * 256;             // 0..1023
        int row = idx >> 3, c = idx & 7;
        if (e < 4) {
            sp[e] = g_ahf + (size_t)(rbase + row) * DDIM + c * 8;
            doff[e] = (uint32_t)(row * 128 + ((c ^ (row & 7)) << 4));
        } else {
            sp[e] = g_whf + (size_t)(jbase + row) * DDIM + c * 8;
            doff[e] = (uint32_t)(16384 + row * 128 + ((c ^ (row & 7)) << 4));
        }
    }

    uint32_t acc[4][4][2];
#pragma unroll
    for (int i = 0; i < 4; ++i)
#pragma unroll
        for (int j = 0; j < 4; ++j) { acc[i][j][0] = 0u; acc[i][j][1] = 0u; }

#define LOAD_STAGE(st, ko)                                                \
    do {                                                                  \
        uint32_t sb_ = smb + (st) * STAGE_B;                              \
        _Pragma("unroll")                                                 \
        for (int e = 0; e < 8; ++e) cp16(sb_ + doff[e], sp[e] + (ko));    \
        asm volatile("cp.async.commit_group;" ::: "memory");              \
    } while (0)

    LOAD_STAGE(0, 0);
    LOAD_STAGE(1, 64);

#pragma unroll
    for (int c = 0; c < 4; ++c) {
        if (c < 3) asm volatile("cp.async.wait_group 1;" ::: "memory");
        else       asm volatile("cp.async.wait_group 0;" ::: "memory");
        __syncthreads();
        if (c < 2) LOAD_STAGE(c + 2 - ((c + 2 >= 3) ? 3 : 0), (c + 2) * 64);
        uint32_t sb = smb + (c % 3) * STAGE_B;
#pragma unroll
        for (int ks = 0; ks < 4; ++ks) {
            uint32_t a[4][4], bf[4][2];
#pragma unroll
            for (int i = 0; i < 4; ++i)
                ldm4(a[i], sb + baseA[i] + (((ks * 2 + hA) ^ vA[i]) << 4));
#pragma unroll
            for (int p = 0; p < 2; ++p) {
                uint32_t r4[4];
                ldm4(r4, sb + baseB[p] + (((ks * 2 + hB) ^ vB[p]) << 4));
                bf[2 * p][0] = r4[0]; bf[2 * p][1] = r4[1];
                bf[2 * p + 1][0] = r4[2]; bf[2 * p + 1][1] = r4[3];
            }
#pragma unroll
            for (int i = 0; i < 4; ++i)
#pragma unroll
                for (int j = 0; j < 4; ++j)
                    mma16816h(acc[i][j], a[i], bf[j]);
        }
    }
#undef LOAD_STAGE

    // epilogue: scores = acc - 0.5*wsq; store bf16; per-row tile max (no atomics)
    const int lq = lane >> 2, lr = lane & 3;
    float bv[8];
#pragma unroll
    for (int s = 0; s < 8; ++s) bv[s] = -3.4e38f;

#pragma unroll
    for (int j = 0; j < 4; ++j) {
        int col = jbase + wn * 32 + j * 8 + lr * 2;
        float2 wq = *reinterpret_cast<const float2*>(&g_wsq[col]);
#pragma unroll
        for (int i = 0; i < 4; ++i) {
#pragma unroll
            for (int h = 0; h < 2; ++h) {
                float2 f = __half22float2(*reinterpret_cast<__half2*>(&acc[i][j][h]));
                float s0 = f.x - 0.5f * wq.x;
                float s1 = f.y - 0.5f * wq.y;
                int grow = rbase + wm * 64 + i * 16 + lq + h * 8;
                __nv_bfloat162 pr = __floats2bfloat162_rn(s0, s1);
                st_cs32(&g_scores[(size_t)grow * VCODES + col],
                        *reinterpret_cast<uint32_t*>(&pr));
                int slot = i * 2 + h;
                bv[slot] = fmaxf(bv[slot], fmaxf(s0, s1));
            }
        }
    }
#pragma unroll
    for (int s = 0; s < 8; ++s) {
#pragma unroll
        for (int o = 1; o < 4; o <<= 1)
            bv[s] = fmaxf(bv[s], __shfl_xor_sync(0xFFFFFFFFu, bv[s], o));
    }
    __syncthreads();                              // done with stage smem
    float* red = (float*)sm;                      // 128 x 4 floats
    if (lr == 0) {
#pragma unroll
        for (int s = 0; s < 8; ++s) {
            int rl = wm * 64 + (s >> 1) * 16 + lq + (s & 1) * 8;
            red[rl * 4 + wn] = bv[s];
        }
    }
    __syncthreads();
    if (tid < 128) {
        float m = fmaxf(fmaxf(red[tid * 4], red[tid * 4 + 1]),
                        fmaxf(red[tid * 4 + 2], red[tid * 4 + 3]));
        g_tilemax[(rbase + tid) * NTILES + blockIdx.x] = enc_f(m);
    }
}

// ---------------------------------------------------------------------------
// Repair: thr from tile maxima; scan flagged tiles' scores; exact fp32
// recompute of candidates. Ascending-j order preserves first-index tie-break.
__global__ void k_repair(const float* __restrict__ x, const float* __restrict__ w,
                         float* __restrict__ out) {
    int r = blockIdx.x * 8 + (threadIdx.x >> 5);
    int lane = threadIdx.x & 31;
    const unsigned* tmrow = g_tilemax + r * NTILES;
    unsigned t0 = tmrow[lane], t1 = tmrow[lane + 32];
    unsigned tmx = max(t0, t1);                   // monotone encoding: u32 max ok
#pragma unroll
    for (int o = 16; o; o >>= 1) tmx = max(tmx, __shfl_xor_sync(0xFFFFFFFFu, tmx, o));
    float thr = dec_f(tmx) - MARGIN;
    int b = r >> 12, s = r & 4095;
    const float* xb = x + (size_t)b * 1048576 + s;
    float bestv = -3.4e38f;
    int   bestj = 0;
    const __nv_bfloat16* srow = g_scores + (size_t)r * VCODES;
#pragma unroll
    for (int half = 0; half < 2; ++half) {
        unsigned tm = half ? t1 : t0;
        unsigned act = __ballot_sync(0xFFFFFFFFu, dec_f(tm) >= thr);
        while (act) {
            int t = __ffs(act) - 1; act &= act - 1;
            int tile = half * 32 + t;
            uint2 v = *reinterpret_cast<const uint2*>(srow + tile * 128 + lane * 4);
            unsigned m = 0;
            unsigned wds[2] = {v.x, v.y};
#pragma unroll
            for (int q = 0; q < 2; ++q) {
                __nv_bfloat162 h2 = *reinterpret_cast<__nv_bfloat162*>(&wds[q]);
                float2 f = __bfloat1622float2(h2);
                if (f.x >= thr) m |= 1u << (2 * q);
                if (f.y >= thr) m |= 1u << (2 * q + 1);
            }
            unsigned act2 = __ballot_sync(0xFFFFFFFFu, m != 0);
            while (act2) {
                int src = __ffs(act2) - 1; act2 &= act2 - 1;
                unsigned mm = __shfl_sync(0xFFFFFFFFu, m, src);
                while (mm) {
                    int bit = __ffs(mm) - 1; mm &= mm - 1;
                    int j = tile * 128 + src * 4 + bit;
                    const float* wr = w + (size_t)j * DDIM;
                    float p = 0.0f;
#pragma unroll
                    for (int q = 0; q < 8; ++q) {
                        int k = lane + q * 32;
                        p += xb[(size_t)k * SPAT] * wr[k];
                    }
#pragma unroll
                    for (int o = 16; o; o >>= 1) p += __shfl_xor_sync(0xFFFFFFFFu, p, o);
                    float sc = p - 0.5f * g_wsq[j];
                    if (sc > bestv) { bestv = sc; bestj = j; }
                }
            }
        }
    }
    if (lane == 0) {
        g_idx[r] = bestj;
        out[O_IDX + r] = (float)bestj;
        atomicAdd(&g_counts[bestj], 1.0f);
    }
}

// ---------------------------------------------------------------------------
// quant write + enc_sum vector reductions + quant_diff. Grid 2048 = 256
// spatial-chunks x 8 d-groups of 32. Thread handles 4 d-quads; per quad:
// one float4 w-gather + one red.v4 (4x fewer LSU slots than scalar).
__global__ void k_assign(const float* __restrict__ x, const float* __restrict__ w,
                         float* __restrict__ out) {
    __shared__ int sidx[128];
    __shared__ float red[8];
    int bi = blockIdx.x;
    int tid = threadIdx.x;
    int sc = bi & 255, dgp = bi >> 8;             // spatial chunk, d-group
    int b = sc >> 5, s0 = (sc & 31) * 128;
    int ts = tid & 127, dh = tid >> 7;
    if (tid < 128) sidx[tid] = g_idx[b * SPAT + s0 + tid];
    __syncthreads();
    int j = sidx[ts];
    const float* wr = w + (size_t)j * DDIM;
    float* er = g_encsum + (size_t)j * DDIM;
    size_t basex = (size_t)b * 1048576 + s0 + ts;
    int d0 = dgp * 32 + dh * 4;                   // quads: d0 + k*8, k=0..3
    float qd = 0.0f;
#pragma unroll
    for (int k = 0; k < 4; ++k) {
        int d = d0 + k * 8;
        float4 wv = __ldg(reinterpret_cast<const float4*>(wr + d));
        size_t off = basex + (size_t)d * SPAT;
        float x0 = x[off];
        float x1 = x[off + SPAT];
        float x2 = x[off + 2 * SPAT];
        float x3 = x[off + 3 * SPAT];
        out[O_QUANT + off]            = (wv.x - x0) + x0;
        out[O_QUANT + off + SPAT]     = (wv.y - x1) + x1;
        out[O_QUANT + off + 2 * SPAT] = (wv.z - x2) + x2;
        out[O_QUANT + off + 3 * SPAT] = (wv.w - x3) + x3;
        float d0f = x0 - wv.x, d1f = x1 - wv.y, d2f = x2 - wv.z, d3f = x3 - wv.w;
        qd += d0f * d0f + d1f * d1f + d2f * d2f + d3f * d3f;
        red4(er + d, x0, x1, x2, x3);
    }
#pragma unroll
    for (int o = 16; o; o >>= 1) qd += __shfl_xor_sync(0xFFFFFFFFu, qd, o);
    if ((tid & 31) == 0) red[tid >> 5] = qd;
    __syncthreads();
    if (tid == 0) {
        float t = 0.0f;
#pragma unroll
        for (int i = 0; i < 8; ++i) t += red[i];
        atomicAdd(&g_qd, t);
    }
}

// ---------------------------------------------------------------------------
__global__ void k_update(const float* __restrict__ N, const float* __restrict__ z_avg,
                         float* __restrict__ out) {
    int i = blockIdx.x * 256 + threadIdx.x;
    if (i >= VCODES * DDIM) return;
    int v = i >> 8, d = i & 255;
    float gamma = 0.99f, om = 0.01f, eps = 1e-7f;
    float n  = gamma * g_sumN + om * (float)MROWS;
    float nN = gamma * N[v] + om * g_counts[v];
    float wgt = (nN + eps) / (n + (float)VCODES * eps) * n;
    float za = gamma * z_avg[i] + om * g_encsum[i];
    out[O_ZAVG + i] = za;
    out[O_NEWW + i] = za / wgt;
    if (d == 0) out[O_NEWN + v] = nN;
    if (i == 0) out[O_QD] = g_qd * (1.0f / 8388608.0f);
}

// ---------------------------------------------------------------------------
extern "C" void kernel_launch(void* const* d_in, const int* in_sizes, int n_in,
                              void* d_out, int out_size) {
    const float* x    = (const float*)d_in[0];
    const float* w    = (const float*)d_in[1];
    const float* N    = (const float*)d_in[2];
    const float* zavg = (const float*)d_in[3];
    float* out = (float*)d_out;

    cudaFuncSetAttribute(k_gemm, cudaFuncAttributeMaxDynamicSharedMemorySize, SMEM_DYN);

    k_prep<<<17409, 256>>>(x, w, N);
    k_gemm<<<dim3(VCODES / 128, MROWS / 128), 256, SMEM_DYN>>>();
    k_repair<<<MROWS / 8, 256>>>(x, w, out);
    k_assign<<<2048, 256>>>(x, w, out);
    k_update<<<VCODES * DDIM / 256, 256>>>(N, zavg, out);
}